// round 12
// baseline (speedup 1.0000x reference)
#include <cuda_runtime.h>
#include <cuda_fp16.h>
#include <cstdint>

#define NBATCH 4
#define HEADS  16
#define QL     2048
#define KVL    2048
#define HD     64
#define ED     1024
#define K2E    0.045084220027780106f   /* (1/sqrt(1024)) * log2(e) */

#define BQ 256
#define BN 64
#define NCHUNK (KVL / BN)
#define PH_PITCH 36   /* words (half2 pairs); %32==4 -> conflict-free frags */

/* scratch: attention output [N, Q, E] fp32 (32 MB) + bit-packed mask (2 MB) */
static __device__ float    g_attn[NBATCH * QL * ED];
static __device__ uint32_t g_maskbits[NBATCH * QL * (KVL / 32)];

/* ----------------------------- small helpers ----------------------------- */
__device__ __forceinline__ uint32_t pack2(float lo, float hi) {
    __half2 h = __floats2half2_rn(lo, hi);
    return *(uint32_t*)&h;
}
__device__ __forceinline__ float ex2f(float x) {
    float r;
    asm("ex2.approx.f32 %0, %1;" : "=f"(r) : "f"(x));
    return r;
}

/* D(16x8,f32) += A(16x16,f16) * B(16x8,f16)  —  m16n8k16 row.col */
__device__ __forceinline__ void mma16(float* d, const uint32_t* a,
                                      uint32_t b0, uint32_t b1) {
    asm volatile(
        "mma.sync.aligned.m16n8k16.row.col.f32.f16.f16.f32 "
        "{%0,%1,%2,%3}, {%4,%5,%6,%7}, {%8,%9}, {%0,%1,%2,%3};"
        : "+f"(d[0]), "+f"(d[1]), "+f"(d[2]), "+f"(d[3])
        : "r"(a[0]), "r"(a[1]), "r"(a[2]), "r"(a[3]), "r"(b0), "r"(b1));
}

/* --------------------------- mask bit-packing ---------------------------- */
__global__ void maskpack(const int* __restrict__ M) {
    int warpid = (blockIdx.x * blockDim.x + threadIdx.x) >> 5;
    int lane = threadIdx.x & 31;
    size_t base = (size_t)warpid * 8;
    #pragma unroll
    for (int t = 0; t < 8; t++) {
        size_t wd = base + t;
        int v = M[wd * 32 + lane];
        uint32_t bits = __ballot_sync(0xffffffffu, v != 0);
        if (lane == 0) g_maskbits[wd] = bits;
    }
}

/* -------------------- fp16 mma.sync flash attention ---------------------- */
/* BQ=256, 8 warps; warp w owns q-rows [w*32, w*32+32) = 2 m16 tiles.
   P register-resident (QK D-frag == PV A-frag). K/V DOUBLE-BUFFERED:
   staging of chunk ch+1 happens mid-chunk (after nsp=1), overlapped with
   MMAs; ONE __syncthreads per chunk.                                        */
__global__ __launch_bounds__(256, 1)
void attn_mma(const float* __restrict__ Q, const float* __restrict__ K,
              const float* __restrict__ V)
{
    extern __shared__ uint32_t sm[];
    uint32_t* KB = sm;                           /* [2][64][36] K (half2)  */
    uint32_t* VB = sm + 2 * 64 * PH_PITCH;       /* [2][64][36] Vt (half2) */
    uint32_t* PH = sm + 4 * 64 * PH_PITCH;       /* [256][36] Q staging    */

    const int tid = threadIdx.x, w = tid >> 5, lane = tid & 31;
    const int g = lane >> 2, c = lane & 3;
    const int n = blockIdx.y >> 4, h = blockIdx.y & 15;
    const int q0 = blockIdx.x * BQ;

    const float* qb = Q + ((size_t)n * QL + q0) * ED + h * HD;
    const float* kb = K + (size_t)n * KVL * ED + h * HD;
    const float* vb = V + (size_t)n * KVL * ED + h * HD;

    /* ---- stage Q (fp16) into PH [256 rows][32 data words] */
    #pragma unroll
    for (int j = 0; j < 16; j++) {
        int flat = tid + 256 * j, r = flat >> 4, d0 = (flat & 15) * 4;
        float4 v = *(const float4*)(qb + (size_t)r * ED + d0);
        uint32_t* d = PH + r * PH_PITCH + d0 / 2;
        d[0] = pack2(v.x, v.y); d[1] = pack2(v.z, v.w);
    }

    /* ---- stage K chunk 0 into buf 0 */
    float4 pk[4];
    #pragma unroll
    for (int j = 0; j < 4; j++) {
        int flat = tid + 256 * j, r = flat >> 4, d0 = (flat & 15) * 4;
        float4 kv4 = *(const float4*)(kb + (size_t)r * ED + d0);
        uint32_t* dk = KB + r * PH_PITCH + d0 / 2;
        dk[0] = pack2(kv4.x, kv4.y); dk[1] = pack2(kv4.z, kv4.w);
        pk[j] = kv4;
    }
    /* ---- stage Vt chunk 0 into buf 0: word (d, rp) = {V[2rp][d], V[2rp+1][d]} */
    const int rp = lane;                 /* kv row-pair index, 0..31 */
    float4 pva[2], pvb[2];
    #pragma unroll
    for (int j = 0; j < 2; j++) {
        int d0 = (w + 8 * j) * 4;
        pva[j] = *(const float4*)(vb + (size_t)(2 * rp) * ED + d0);
        pvb[j] = *(const float4*)(vb + (size_t)(2 * rp + 1) * ED + d0);
        float a4[4] = {pva[j].x, pva[j].y, pva[j].z, pva[j].w};
        float b4[4] = {pvb[j].x, pvb[j].y, pvb[j].z, pvb[j].w};
        #pragma unroll
        for (int e = 0; e < 4; e++)
            VB[(d0 + e) * PH_PITCH + rp] = pack2(a4[e], b4[e]);
    }
    __syncthreads();

    /* ---- resident Q A-fragments: 2 tiles x 4 ks16 x 4 regs */
    uint32_t aQ[2][4][4];
    #pragma unroll
    for (int mi = 0; mi < 2; mi++) {
        int rb = w * 32 + mi * 16;
        #pragma unroll
        for (int ks = 0; ks < 4; ks++) {
            const uint32_t* p0 = PH + (rb + g) * PH_PITCH + ks * 8 + c;
            const uint32_t* p1 = p0 + 8 * PH_PITCH;
            aQ[mi][ks][0] = p0[0]; aQ[mi][ks][2] = p0[4];
            aQ[mi][ks][1] = p1[0]; aQ[mi][ks][3] = p1[4];
        }
    }

    float Oa[2][8][4];
    #pragma unroll
    for (int mi = 0; mi < 2; mi++)
        #pragma unroll
        for (int i = 0; i < 8; i++)
            #pragma unroll
            for (int j = 0; j < 4; j++) Oa[mi][i][j] = 0.0f;
    float rs00 = 0.0f, rs01 = 0.0f, rs10 = 0.0f, rs11 = 0.0f;

    const unsigned long long* mbase = (const unsigned long long*)g_maskbits;
    const unsigned long long* mp00 = mbase + (size_t)(n * QL + q0 + w * 32 + g) * 32;
    const unsigned long long* mp01 = mp00 + 8 * 32;
    const unsigned long long* mp10 = mp00 + 16 * 32;
    const unsigned long long* mp11 = mp00 + 24 * 32;

    for (int ch = 0; ch < NCHUNK; ch++) {
        const int p = ch & 1;
        const bool more = (ch + 1 < NCHUNK);
        uint32_t* KS = KB + p * 64 * PH_PITCH;
        uint32_t* VS = VB + p * 64 * PH_PITCH;
        uint32_t* KN = KB + (1 - p) * 64 * PH_PITCH;
        uint32_t* VN = VB + (1 - p) * 64 * PH_PITCH;

        /* issue gmem loads for chunk ch+1 (land during nsp 0-1) */
        if (more) {
            const float* kn = kb + (size_t)(ch + 1) * BN * ED;
            const float* vn = vb + (size_t)(ch + 1) * BN * ED;
            #pragma unroll
            for (int j = 0; j < 4; j++) {
                int flat = tid + 256 * j, r = flat >> 4, d0 = (flat & 15) * 4;
                pk[j] = *(const float4*)(kn + (size_t)r * ED + d0);
            }
            #pragma unroll
            for (int j = 0; j < 2; j++) {
                int d0 = (w + 8 * j) * 4;
                pva[j] = *(const float4*)(vn + (size_t)(2 * rp) * ED + d0);
                pvb[j] = *(const float4*)(vn + (size_t)(2 * rp + 1) * ED + d0);
            }
        }

        unsigned long long m00 = mp00[ch], m01 = mp01[ch];
        unsigned long long m10 = mp10[ch], m11 = mp11[ch];

        /* ---- per nsp (16 kv): QK -> softmax (registers) -> PV.
           After nsp==1, stage chunk ch+1 into the other buffer (overlaps). */
        #pragma unroll
        for (int nsp = 0; nsp < 4; nsp++) {
            if (nsp == 2 && more) {
                #pragma unroll
                for (int j = 0; j < 4; j++) {
                    int flat = tid + 256 * j, r = flat >> 4, d0 = (flat & 15) * 4;
                    uint32_t* dk = KN + r * PH_PITCH + d0 / 2;
                    dk[0] = pack2(pk[j].x, pk[j].y);
                    dk[1] = pack2(pk[j].z, pk[j].w);
                }
                #pragma unroll
                for (int j = 0; j < 2; j++) {
                    int d0 = (w + 8 * j) * 4;
                    float a4[4] = {pva[j].x, pva[j].y, pva[j].z, pva[j].w};
                    float b4[4] = {pvb[j].x, pvb[j].y, pvb[j].z, pvb[j].w};
                    #pragma unroll
                    for (int e = 0; e < 4; e++)
                        VN[(d0 + e) * PH_PITCH + rp] = pack2(a4[e], b4[e]);
                }
            }

            float S[2][2][4];
            #pragma unroll
            for (int mi = 0; mi < 2; mi++)
                #pragma unroll
                for (int nn = 0; nn < 2; nn++)
                    #pragma unroll
                    for (int j = 0; j < 4; j++) S[mi][nn][j] = 0.0f;

            #pragma unroll
            for (int ks = 0; ks < 4; ks++) {
                #pragma unroll
                for (int nn = 0; nn < 2; nn++) {
                    int ns = nsp * 2 + nn;
                    const uint32_t* bp = KS + (ns * 8 + g) * PH_PITCH + ks * 8 + c;
                    uint32_t b0 = bp[0], b1 = bp[4];
                    mma16(S[0][nn], aQ[0][ks], b0, b1);
                    mma16(S[1][nn], aQ[1][ks], b0, b1);
                }
            }

            /* softmax -> P A-fragments directly in registers */
            uint32_t aP0[4], aP1[4];
            #pragma unroll
            for (int nn = 0; nn < 2; nn++) {
                int ns = nsp * 2 + nn;
                int sh = ns * 8 + 2 * c;
                {   /* tile mi = 0 */
                    uint32_t bm0 = (uint32_t)(m00 >> sh);
                    uint32_t bm1 = (uint32_t)(m01 >> sh);
                    float e0 = (bm0 & 1u) ? ex2f(S[0][nn][0] * K2E) : 0.0f;
                    float e1 = (bm0 & 2u) ? ex2f(S[0][nn][1] * K2E) : 0.0f;
                    float e2 = (bm1 & 1u) ? ex2f(S[0][nn][2] * K2E) : 0.0f;
                    float e3 = (bm1 & 2u) ? ex2f(S[0][nn][3] * K2E) : 0.0f;
                    rs00 += e0 + e1;
                    rs01 += e2 + e3;
                    aP0[2 * nn]     = pack2(e0, e1);
                    aP0[2 * nn + 1] = pack2(e2, e3);
                }
                {   /* tile mi = 1 */
                    uint32_t bm0 = (uint32_t)(m10 >> sh);
                    uint32_t bm1 = (uint32_t)(m11 >> sh);
                    float e0 = (bm0 & 1u) ? ex2f(S[1][nn][0] * K2E) : 0.0f;
                    float e1 = (bm0 & 2u) ? ex2f(S[1][nn][1] * K2E) : 0.0f;
                    float e2 = (bm1 & 1u) ? ex2f(S[1][nn][2] * K2E) : 0.0f;
                    float e3 = (bm1 & 2u) ? ex2f(S[1][nn][3] * K2E) : 0.0f;
                    rs10 += e0 + e1;
                    rs11 += e2 + e3;
                    aP1[2 * nn]     = pack2(e0, e1);
                    aP1[2 * nn + 1] = pack2(e2, e3);
                }
            }

            /* ---- O += P V for this 16-kv slice (B frags from Vt smem) */
            #pragma unroll
            for (int ds = 0; ds < 8; ds++) {
                const uint32_t* vp = VS + (ds * 8 + g) * PH_PITCH + nsp * 8 + c;
                uint32_t b0 = vp[0], b1 = vp[4];
                mma16(Oa[0][ds], aP0, b0, b1);
                mma16(Oa[1][ds], aP1, b0, b1);
            }
        }

        /* one sync per chunk: buf 1-p published; reads of buf p complete */
        __syncthreads();
    }

    /* row-sum reduce across quad, normalize, write */
    rs00 += __shfl_xor_sync(0xffffffffu, rs00, 1);
    rs00 += __shfl_xor_sync(0xffffffffu, rs00, 2);
    rs01 += __shfl_xor_sync(0xffffffffu, rs01, 1);
    rs01 += __shfl_xor_sync(0xffffffffu, rs01, 2);
    rs10 += __shfl_xor_sync(0xffffffffu, rs10, 1);
    rs10 += __shfl_xor_sync(0xffffffffu, rs10, 2);
    rs11 += __shfl_xor_sync(0xffffffffu, rs11, 1);
    rs11 += __shfl_xor_sync(0xffffffffu, rs11, 2);

    #pragma unroll
    for (int mi = 0; mi < 2; mi++) {
        float inv0 = 1.0f / (mi ? rs10 : rs00);
        float inv1 = 1.0f / (mi ? rs11 : rs01);
        float* ob0 = g_attn
            + (size_t)(n * QL + q0 + w * 32 + mi * 16 + g) * ED + h * HD;
        float* ob1 = ob0 + (size_t)8 * ED;
        #pragma unroll
        for (int ds = 0; ds < 8; ds++) {
            *(float2*)(ob0 + ds * 8 + 2 * c) =
                make_float2(Oa[mi][ds][0] * inv0, Oa[mi][ds][1] * inv0);
            *(float2*)(ob1 + ds * 8 + 2 * c) =
                make_float2(Oa[mi][ds][2] * inv1, Oa[mi][ds][3] * inv1);
        }
    }
}

/* ------------- projection Y = X W^T + b (fp16 mma, f32 accum) ------------ */
__global__ __launch_bounds__(256, 2)
void proj_mma(const float* __restrict__ W, const float* __restrict__ bias,
              float* __restrict__ Y)
{
    extern __shared__ uint32_t ps[];
    uint32_t* XH = ps;                       /* [128][36] half2 */
    uint32_t* WS = ps + 128 * PH_PITCH;

    const int tid = threadIdx.x, w = tid >> 5, lane = tid & 31;
    const int g = lane >> 2, c = lane & 3;
    const int wm = w & 3, wn = w >> 2;
    const int m0 = blockIdx.y * 128, n0 = blockIdx.x * 128;
    const float* X = g_attn;

    float D[2][8][4];
    #pragma unroll
    for (int a = 0; a < 2; a++)
        #pragma unroll
        for (int i = 0; i < 8; i++)
            #pragma unroll
            for (int j = 0; j < 4; j++) D[a][i][j] = 0.0f;

    for (int kt = 0; kt < 32; kt++) {
        const int k0 = kt * 32;
        __syncthreads();
        #pragma unroll
        for (int j = 0; j < 4; j++) {
            int flat = tid + 256 * j, r = flat >> 3, c4 = flat & 7;
            float4 xv = *(const float4*)(X + (size_t)(m0 + r) * ED + k0 + c4 * 4);
            uint32_t* dh = XH + r * PH_PITCH + c4 * 2;
            dh[0] = pack2(xv.x, xv.y); dh[1] = pack2(xv.z, xv.w);
            float4 wv = *(const float4*)(W + (size_t)(n0 + r) * ED + k0 + c4 * 4);
            uint32_t* dw = WS + r * PH_PITCH + c4 * 2;
            dw[0] = pack2(wv.x, wv.y); dw[1] = pack2(wv.z, wv.w);
        }
        __syncthreads();

        #pragma unroll
        for (int ks = 0; ks < 2; ks++) {
            uint32_t A[2][4];
            #pragma unroll
            for (int mi = 0; mi < 2; mi++) {
                int rb = wm * 32 + mi * 16;
                const uint32_t* p0 = XH + (rb + g) * PH_PITCH + ks * 8 + c;
                const uint32_t* p1 = XH + (rb + g + 8) * PH_PITCH + ks * 8 + c;
                A[mi][0] = p0[0]; A[mi][2] = p0[4];
                A[mi][1] = p1[0]; A[mi][3] = p1[4];
            }
            #pragma unroll
            for (int ns = 0; ns < 8; ns++) {
                const uint32_t* bp =
                    WS + (wn * 64 + ns * 8 + g) * PH_PITCH + ks * 8 + c;
                uint32_t b0 = bp[0], b1 = bp[4];
                mma16(D[0][ns], A[0], b0, b1);
                mma16(D[1][ns], A[1], b0, b1);
            }
        }
    }

    #pragma unroll
    for (int mi = 0; mi < 2; mi++) {
        int row0 = m0 + wm * 32 + mi * 16 + g;
        #pragma unroll
        for (int ns = 0; ns < 8; ns++) {
            int col = n0 + wn * 64 + ns * 8 + 2 * c;
            float2 bv = *(const float2*)(bias + col);
            *(float2*)(Y + (size_t)row0 * ED + col) =
                make_float2(D[mi][ns][0] + bv.x, D[mi][ns][1] + bv.y);
            *(float2*)(Y + (size_t)(row0 + 8) * ED + col) =
                make_float2(D[mi][ns][2] + bv.x, D[mi][ns][3] + bv.y);
        }
    }
}

/* --------------------------------- launch -------------------------------- */
extern "C" void kernel_launch(void* const* d_in, const int* in_sizes, int n_in,
                              void* d_out, int out_size)
{
    const float* q    = (const float*)d_in[0];
    const float* k    = (const float*)d_in[1];
    const float* v    = (const float*)d_in[2];
    const int*   mask = (const int*)  d_in[3];
    const float* W    = (const float*)d_in[4];
    const float* b    = (const float*)d_in[5];
    float* out = (float*)d_out;

    const int smem_attn = (4 * 64 + 256) * PH_PITCH * 4;   /* 73728 */
    const int smem_proj = 2 * 128 * PH_PITCH * 4;          /* 36864 */
    cudaFuncSetAttribute(attn_mma, cudaFuncAttributeMaxDynamicSharedMemorySize, smem_attn);
    cudaFuncSetAttribute(proj_mma, cudaFuncAttributeMaxDynamicSharedMemorySize, smem_proj);

    maskpack<<<8192, 256>>>(mask);

    dim3 g1(QL / BQ, NBATCH * HEADS);
    attn_mma<<<g1, 256, smem_attn>>>(q, k, v);

    dim3 g2(ED / 128, (NBATCH * QL) / 128);
    proj_mma<<<g2, 256, smem_proj>>>(W, b, out);
}

// round 13
// speedup vs baseline: 1.0984x; 1.0984x over previous
#include <cuda_runtime.h>
#include <cuda_fp16.h>
#include <cstdint>

#define NBATCH 4
#define HEADS  16
#define QL     2048
#define KVL    2048
#define HD     64
#define ED     1024
#define K2E    0.045084220027780106f   /* (1/sqrt(1024)) * log2(e) */

#define BQ 128
#define BN 64
#define NCHUNK (KVL / BN)
#define PH_PITCH 36   /* words (half2 pairs); %32==4 -> conflict-free frags */

/* scratch: attention output [N, Q, E] fp32 (32 MB) + bit-packed mask (2 MB) */
static __device__ float    g_attn[NBATCH * QL * ED];
static __device__ uint32_t g_maskbits[NBATCH * QL * (KVL / 32)];

/* ----------------------------- small helpers ----------------------------- */
__device__ __forceinline__ uint32_t pack2(float lo, float hi) {
    __half2 h = __floats2half2_rn(lo, hi);
    return *(uint32_t*)&h;
}
__device__ __forceinline__ float ex2f(float x) {
    float r;
    asm("ex2.approx.f32 %0, %1;" : "=f"(r) : "f"(x));
    return r;
}

/* D(16x8,f32) += A(16x16,f16) * B(16x8,f16)  —  m16n8k16 row.col */
__device__ __forceinline__ void mma16(float* d, const uint32_t* a,
                                      uint32_t b0, uint32_t b1) {
    asm volatile(
        "mma.sync.aligned.m16n8k16.row.col.f32.f16.f16.f32 "
        "{%0,%1,%2,%3}, {%4,%5,%6,%7}, {%8,%9}, {%0,%1,%2,%3};"
        : "+f"(d[0]), "+f"(d[1]), "+f"(d[2]), "+f"(d[3])
        : "r"(a[0]), "r"(a[1]), "r"(a[2]), "r"(a[3]), "r"(b0), "r"(b1));
}

/* --------------------------- mask bit-packing ---------------------------- */
__global__ void maskpack(const int* __restrict__ M) {
    int warpid = (blockIdx.x * blockDim.x + threadIdx.x) >> 5;
    int lane = threadIdx.x & 31;
    size_t base = (size_t)warpid * 8;
    #pragma unroll
    for (int t = 0; t < 8; t++) {
        size_t wd = base + t;
        int v = M[wd * 32 + lane];
        uint32_t bits = __ballot_sync(0xffffffffu, v != 0);
        if (lane == 0) g_maskbits[wd] = bits;
    }
}

/* -------------------- fp16 mma.sync flash attention ---------------------- */
/* BQ=128, 8 warps; warp w owns ONE m16 tile (q-rows [w*16, w*16+16)).
   ~90 regs -> 2 CTAs/SM (4 warps/SMSP): one CTA's MMAs hide the other's
   softmax/MUFU and staging latency. P register-resident (QK D == PV A).    */
__global__ __launch_bounds__(256, 2)
void attn_mma(const float* __restrict__ Q, const float* __restrict__ K,
              const float* __restrict__ V)
{
    extern __shared__ uint32_t sm[];
    uint32_t* KS = sm;                          /* [64][36]  K  (half2)    */
    uint32_t* VS = sm + 64 * PH_PITCH;          /* [64][36]  Vt (half2)    */
    uint32_t* PH = sm + 2 * 64 * PH_PITCH;      /* [128][36] Q staging     */

    const int tid = threadIdx.x, w = tid >> 5, lane = tid & 31;
    const int g = lane >> 2, c = lane & 3;
    const int n = blockIdx.y >> 4, h = blockIdx.y & 15;
    const int q0 = blockIdx.x * BQ;

    const float* qb = Q + ((size_t)n * QL + q0) * ED + h * HD;
    const float* kb = K + (size_t)n * KVL * ED + h * HD;
    const float* vb = V + (size_t)n * KVL * ED + h * HD;

    /* ---- stage Q (fp16) into PH [128 rows][32 data words] */
    #pragma unroll
    for (int j = 0; j < 8; j++) {
        int flat = tid + 256 * j, r = flat >> 4, d0 = (flat & 15) * 4;
        float4 v = *(const float4*)(qb + (size_t)r * ED + d0);
        uint32_t* d = PH + r * PH_PITCH + d0 / 2;
        d[0] = pack2(v.x, v.y); d[1] = pack2(v.z, v.w);
    }
    __syncthreads();

    /* ---- resident Q A-fragments: 4 ks16 x 4 regs */
    uint32_t aQ[4][4];
    {
        int rb = w * 16;
        #pragma unroll
        for (int ks = 0; ks < 4; ks++) {
            const uint32_t* p0 = PH + (rb + g) * PH_PITCH + ks * 8 + c;
            const uint32_t* p1 = p0 + 8 * PH_PITCH;
            aQ[ks][0] = p0[0]; aQ[ks][2] = p0[4];
            aQ[ks][1] = p1[0]; aQ[ks][3] = p1[4];
        }
    }

    float Oa[8][4];
    #pragma unroll
    for (int i = 0; i < 8; i++)
        #pragma unroll
        for (int j = 0; j < 4; j++) Oa[i][j] = 0.0f;
    float rs0 = 0.0f, rs1 = 0.0f;

    const unsigned long long* mbase = (const unsigned long long*)g_maskbits;
    const unsigned long long* mp0 = mbase + (size_t)(n * QL + q0 + w * 16 + g) * 32;
    const unsigned long long* mp1 = mp0 + 8 * 32;

    const int rp = lane;   /* kv row-pair index for Vt staging */

    for (int ch = 0; ch < NCHUNK; ch++) {
        __syncthreads();   /* previous chunk's reads of KS/VS complete */

        /* ---- stage K chunk: rows kv, words = d pairs */
        const float* kc = kb + (size_t)ch * BN * ED;
        const float* vc = vb + (size_t)ch * BN * ED;
        #pragma unroll
        for (int j = 0; j < 4; j++) {
            int flat = tid + 256 * j, r = flat >> 4, d0 = (flat & 15) * 4;
            float4 kv4 = *(const float4*)(kc + (size_t)r * ED + d0);
            uint32_t* dk = KS + r * PH_PITCH + d0 / 2;
            dk[0] = pack2(kv4.x, kv4.y); dk[1] = pack2(kv4.z, kv4.w);
        }
        /* ---- stage Vt: word (d, rp) = {V[2rp][d], V[2rp+1][d]} */
        #pragma unroll
        for (int j = 0; j < 2; j++) {
            int d0 = (w + 8 * j) * 4;
            float4 va = *(const float4*)(vc + (size_t)(2 * rp) * ED + d0);
            float4 vbq = *(const float4*)(vc + (size_t)(2 * rp + 1) * ED + d0);
            float a4[4] = {va.x, va.y, va.z, va.w};
            float b4[4] = {vbq.x, vbq.y, vbq.z, vbq.w};
            #pragma unroll
            for (int e = 0; e < 4; e++)
                VS[(d0 + e) * PH_PITCH + rp] = pack2(a4[e], b4[e]);
        }
        __syncthreads();

        unsigned long long m0 = mp0[ch];
        unsigned long long m1 = mp1[ch];

        /* ---- per nsp (16 kv): QK -> softmax (registers) -> PV */
        #pragma unroll
        for (int nsp = 0; nsp < 4; nsp++) {
            float S[2][4];
            #pragma unroll
            for (int nn = 0; nn < 2; nn++)
                #pragma unroll
                for (int j = 0; j < 4; j++) S[nn][j] = 0.0f;

            #pragma unroll
            for (int ks = 0; ks < 4; ks++) {
                #pragma unroll
                for (int nn = 0; nn < 2; nn++) {
                    int ns = nsp * 2 + nn;
                    const uint32_t* bp = KS + (ns * 8 + g) * PH_PITCH + ks * 8 + c;
                    mma16(S[nn], aQ[ks], bp[0], bp[4]);
                }
            }

            /* softmax -> P A-fragment directly in registers */
            uint32_t aP[4];
            #pragma unroll
            for (int nn = 0; nn < 2; nn++) {
                int ns = nsp * 2 + nn;
                int sh = ns * 8 + 2 * c;
                uint32_t bm0 = (uint32_t)(m0 >> sh);
                uint32_t bm1 = (uint32_t)(m1 >> sh);
                float e0 = (bm0 & 1u) ? ex2f(S[nn][0] * K2E) : 0.0f;
                float e1 = (bm0 & 2u) ? ex2f(S[nn][1] * K2E) : 0.0f;
                float e2 = (bm1 & 1u) ? ex2f(S[nn][2] * K2E) : 0.0f;
                float e3 = (bm1 & 2u) ? ex2f(S[nn][3] * K2E) : 0.0f;
                rs0 += e0 + e1;
                rs1 += e2 + e3;
                aP[2 * nn]     = pack2(e0, e1);
                aP[2 * nn + 1] = pack2(e2, e3);
            }

            /* ---- O += P V for this 16-kv slice (B frags from Vt smem) */
            #pragma unroll
            for (int ds = 0; ds < 8; ds++) {
                const uint32_t* vp = VS + (ds * 8 + g) * PH_PITCH + nsp * 8 + c;
                mma16(Oa[ds], aP, vp[0], vp[4]);
            }
        }
    }

    /* row-sum reduce across quad, normalize, write */
    rs0 += __shfl_xor_sync(0xffffffffu, rs0, 1);
    rs0 += __shfl_xor_sync(0xffffffffu, rs0, 2);
    rs1 += __shfl_xor_sync(0xffffffffu, rs1, 1);
    rs1 += __shfl_xor_sync(0xffffffffu, rs1, 2);
    float inv0 = 1.0f / rs0, inv1 = 1.0f / rs1;

    float* ob0 = g_attn + (size_t)(n * QL + q0 + w * 16 + g) * ED + h * HD;
    float* ob1 = ob0 + (size_t)8 * ED;
    #pragma unroll
    for (int ds = 0; ds < 8; ds++) {
        *(float2*)(ob0 + ds * 8 + 2 * c) =
            make_float2(Oa[ds][0] * inv0, Oa[ds][1] * inv0);
        *(float2*)(ob1 + ds * 8 + 2 * c) =
            make_float2(Oa[ds][2] * inv1, Oa[ds][3] * inv1);
    }
}

/* ------------- projection Y = X W^T + b (fp16 mma, f32 accum) ------------ */
__global__ __launch_bounds__(256, 2)
void proj_mma(const float* __restrict__ W, const float* __restrict__ bias,
              float* __restrict__ Y)
{
    extern __shared__ uint32_t ps[];
    uint32_t* XH = ps;                       /* [128][36] half2 */
    uint32_t* WS = ps + 128 * PH_PITCH;

    const int tid = threadIdx.x, w = tid >> 5, lane = tid & 31;
    const int g = lane >> 2, c = lane & 3;
    const int wm = w & 3, wn = w >> 2;
    const int m0 = blockIdx.y * 128, n0 = blockIdx.x * 128;
    const float* X = g_attn;

    float D[2][8][4];
    #pragma unroll
    for (int a = 0; a < 2; a++)
        #pragma unroll
        for (int i = 0; i < 8; i++)
            #pragma unroll
            for (int j = 0; j < 4; j++) D[a][i][j] = 0.0f;

    for (int kt = 0; kt < 32; kt++) {
        const int k0 = kt * 32;
        __syncthreads();
        #pragma unroll
        for (int j = 0; j < 4; j++) {
            int flat = tid + 256 * j, r = flat >> 3, c4 = flat & 7;
            float4 xv = *(const float4*)(X + (size_t)(m0 + r) * ED + k0 + c4 * 4);
            uint32_t* dh = XH + r * PH_PITCH + c4 * 2;
            dh[0] = pack2(xv.x, xv.y); dh[1] = pack2(xv.z, xv.w);
            float4 wv = *(const float4*)(W + (size_t)(n0 + r) * ED + k0 + c4 * 4);
            uint32_t* dw = WS + r * PH_PITCH + c4 * 2;
            dw[0] = pack2(wv.x, wv.y); dw[1] = pack2(wv.z, wv.w);
        }
        __syncthreads();

        #pragma unroll
        for (int ks = 0; ks < 2; ks++) {
            uint32_t A[2][4];
            #pragma unroll
            for (int mi = 0; mi < 2; mi++) {
                int rb = wm * 32 + mi * 16;
                const uint32_t* p0 = XH + (rb + g) * PH_PITCH + ks * 8 + c;
                const uint32_t* p1 = XH + (rb + g + 8) * PH_PITCH + ks * 8 + c;
                A[mi][0] = p0[0]; A[mi][2] = p0[4];
                A[mi][1] = p1[0]; A[mi][3] = p1[4];
            }
            #pragma unroll
            for (int ns = 0; ns < 8; ns++) {
                const uint32_t* bp =
                    WS + (wn * 64 + ns * 8 + g) * PH_PITCH + ks * 8 + c;
                uint32_t b0 = bp[0], b1 = bp[4];
                mma16(D[0][ns], A[0], b0, b1);
                mma16(D[1][ns], A[1], b0, b1);
            }
        }
    }

    #pragma unroll
    for (int mi = 0; mi < 2; mi++) {
        int row0 = m0 + wm * 32 + mi * 16 + g;
        #pragma unroll
        for (int ns = 0; ns < 8; ns++) {
            int col = n0 + wn * 64 + ns * 8 + 2 * c;
            float2 bv = *(const float2*)(bias + col);
            *(float2*)(Y + (size_t)row0 * ED + col) =
                make_float2(D[mi][ns][0] + bv.x, D[mi][ns][1] + bv.y);
            *(float2*)(Y + (size_t)(row0 + 8) * ED + col) =
                make_float2(D[mi][ns][2] + bv.x, D[mi][ns][3] + bv.y);
        }
    }
}

/* --------------------------------- launch -------------------------------- */
extern "C" void kernel_launch(void* const* d_in, const int* in_sizes, int n_in,
                              void* d_out, int out_size)
{
    const float* q    = (const float*)d_in[0];
    const float* k    = (const float*)d_in[1];
    const float* v    = (const float*)d_in[2];
    const int*   mask = (const int*)  d_in[3];
    const float* W    = (const float*)d_in[4];
    const float* b    = (const float*)d_in[5];
    float* out = (float*)d_out;

    const int smem_attn = (2 * 64 + 128) * PH_PITCH * 4;   /* 36864 */
    const int smem_proj = 2 * 128 * PH_PITCH * 4;          /* 36864 */
    cudaFuncSetAttribute(attn_mma, cudaFuncAttributeMaxDynamicSharedMemorySize, smem_attn);
    cudaFuncSetAttribute(proj_mma, cudaFuncAttributeMaxDynamicSharedMemorySize, smem_proj);

    maskpack<<<8192, 256>>>(mask);

    dim3 g1(QL / BQ, NBATCH * HEADS);
    attn_mma<<<g1, 256, smem_attn>>>(q, k, v);

    dim3 g2(ED / 128, (NBATCH * QL) / 128);
    proj_mma<<<g2, 256, smem_proj>>>(W, b, out);
}

// round 14
// speedup vs baseline: 1.4125x; 1.2859x over previous
#include <cuda_runtime.h>
#include <cuda_fp16.h>
#include <cstdint>

#define NBATCH 4
#define HEADS  16
#define NH     (NBATCH * HEADS)
#define QL     2048
#define KVL    2048
#define HD     64
#define ED     1024
#define K2E    0.045084220027780106f   /* (1/sqrt(1024)) * log2(e) */

#define BQ 128
#define BN 64
#define NCHUNK (KVL / BN)
#define PH_PITCH 36   /* words (half2 pairs); %32==4 -> conflict-free frags */

/* pre-converted fp16 operand layouts (device scratch) */
static __device__ uint32_t g_Qh[(size_t)NH * QL * 32];          /* [nh][q][d/2]  */
static __device__ uint32_t g_Kh[(size_t)NH * KVL * 32];         /* [nh][kv][d/2] */
static __device__ uint32_t g_Vt[(size_t)NH * HD * (KVL / 2)];   /* [nh][d][rp]   */
static __device__ uint32_t g_Xh[(size_t)NBATCH * QL * (ED / 2)];/* attn out fp16 */
static __device__ uint32_t g_Wh[(size_t)ED * (ED / 2)];         /* W fp16        */
static __device__ uint32_t g_maskbits[NBATCH * QL * (KVL / 32)];

/* ----------------------------- small helpers ----------------------------- */
__device__ __forceinline__ uint32_t pack2(float lo, float hi) {
    __half2 h = __floats2half2_rn(lo, hi);
    return *(uint32_t*)&h;
}
__device__ __forceinline__ float ex2f(float x) {
    float r;
    asm("ex2.approx.f32 %0, %1;" : "=f"(r) : "f"(x));
    return r;
}
__device__ __forceinline__ uint32_t smem_u32(const void* p) {
    uint32_t a;
    asm("{ .reg .u64 t; cvta.to.shared.u64 t, %1; cvt.u32.u64 %0, t; }"
        : "=r"(a) : "l"(p));
    return a;
}
__device__ __forceinline__ void cp16(uint32_t dst, const void* src) {
    asm volatile("cp.async.cg.shared.global [%0], [%1], 16;"
                 :: "r"(dst), "l"(src) : "memory");
}
#define CP_COMMIT() asm volatile("cp.async.commit_group;" ::: "memory")
#define CP_WAIT0()  asm volatile("cp.async.wait_group 0;" ::: "memory")

/* D(16x8,f32) += A(16x16,f16) * B(16x8,f16)  —  m16n8k16 row.col */
__device__ __forceinline__ void mma16(float* d, const uint32_t* a,
                                      uint32_t b0, uint32_t b1) {
    asm volatile(
        "mma.sync.aligned.m16n8k16.row.col.f32.f16.f16.f32 "
        "{%0,%1,%2,%3}, {%4,%5,%6,%7}, {%8,%9}, {%0,%1,%2,%3};"
        : "+f"(d[0]), "+f"(d[1]), "+f"(d[2]), "+f"(d[3])
        : "r"(a[0]), "r"(a[1]), "r"(a[2]), "r"(a[3]), "r"(b0), "r"(b1));
}

/* ------------------------------ pre-kernels ------------------------------ */
__global__ void maskpack(const int* __restrict__ M) {
    int warpid = (blockIdx.x * blockDim.x + threadIdx.x) >> 5;
    int lane = threadIdx.x & 31;
    size_t base = (size_t)warpid * 8;
    #pragma unroll
    for (int t = 0; t < 8; t++) {
        size_t wd = base + t;
        int v = M[wd * 32 + lane];
        uint32_t bits = __ballot_sync(0xffffffffu, v != 0);
        if (lane == 0) g_maskbits[wd] = bits;
    }
}

/* Q,K -> head-major fp16 rows */
__global__ __launch_bounds__(256) void convQK(const float* __restrict__ Q,
                                              const float* __restrict__ K) {
    int nh = blockIdx.y, n = nh >> 4, h = nh & 15;
    int r0 = blockIdx.x * 128;
    int tid = threadIdx.x;
    const float* qs = Q + ((size_t)n * QL + r0) * ED + h * HD;
    const float* ks = K + ((size_t)n * KVL + r0) * ED + h * HD;
    uint32_t* qd = g_Qh + ((size_t)nh * QL + r0) * 32;
    uint32_t* kd = g_Kh + ((size_t)nh * KVL + r0) * 32;
    #pragma unroll
    for (int j = 0; j < 8; j++) {
        int flat = tid + 256 * j, r = flat >> 4, d0 = (flat & 15) * 4;
        float4 a = *(const float4*)(qs + (size_t)r * ED + d0);
        qd[r * 32 + d0 / 2]     = pack2(a.x, a.y);
        qd[r * 32 + d0 / 2 + 1] = pack2(a.z, a.w);
        float4 b = *(const float4*)(ks + (size_t)r * ED + d0);
        kd[r * 32 + d0 / 2]     = pack2(b.x, b.y);
        kd[r * 32 + d0 / 2 + 1] = pack2(b.z, b.w);
    }
}

/* V -> transposed half2 image: word(d, rp) = {V[2rp][d], V[2rp+1][d]} */
__global__ __launch_bounds__(256) void convV(const float* __restrict__ V) {
    int nh = blockIdx.y, n = nh >> 4, h = nh & 15;
    int rp = blockIdx.x * 32 + (threadIdx.x & 31);
    int w = threadIdx.x >> 5;
    const float* vs = V + (size_t)n * KVL * ED + h * HD;
    uint32_t* vd = g_Vt + (size_t)nh * HD * (KVL / 2);
    #pragma unroll
    for (int j = 0; j < 2; j++) {
        int d0 = (w * 2 + j) * 4;
        float4 a = *(const float4*)(vs + (size_t)(2 * rp) * ED + d0);
        float4 b = *(const float4*)(vs + (size_t)(2 * rp + 1) * ED + d0);
        vd[(d0 + 0) * (KVL / 2) + rp] = pack2(a.x, b.x);
        vd[(d0 + 1) * (KVL / 2) + rp] = pack2(a.y, b.y);
        vd[(d0 + 2) * (KVL / 2) + rp] = pack2(a.z, b.z);
        vd[(d0 + 3) * (KVL / 2) + rp] = pack2(a.w, b.w);
    }
}

__global__ void convW(const float* __restrict__ W) {
    int flat = blockIdx.x * 256 + threadIdx.x;   /* 262144 float4s */
    float4 v = *(const float4*)(W + (size_t)flat * 4);
    g_Wh[flat * 2]     = pack2(v.x, v.y);
    g_Wh[flat * 2 + 1] = pack2(v.z, v.w);
}

/* -------------------- fp16 mma.sync flash attention ---------------------- */
/* BQ=128, 8 warps, occ 2. All staging = cp.async from pre-converted fp16
   layouts (no registers, no cvt, no STS). K/V double-buffered; one
   wait+sync per chunk. P register-resident (QK D-frag == PV A-frag).       */
__global__ __launch_bounds__(256, 2) void attn_mma() {
    extern __shared__ uint32_t sm[];
    uint32_t* smK = sm;            /* 2 bufs @ 0, 2304 (words)  */
    uint32_t* smV = sm + 4608;     /* 2 bufs @ 4608, 6912       */
    uint32_t* QS  = sm + 9216;     /* [128][36] Q fragments     */
    const uint32_t sbase = smem_u32(sm);
    const uint32_t KSb = sbase;
    const uint32_t VSb = sbase + 4608 * 4;
    const uint32_t QSb = sbase + 9216 * 4;

    const int tid = threadIdx.x, w = tid >> 5, lane = tid & 31;
    const int g = lane >> 2, c = lane & 3;
    const int nh = blockIdx.y, n = nh >> 4;
    const int q0 = blockIdx.x * BQ;

    const uint32_t* Qg = g_Qh + ((size_t)nh * QL + q0) * 32;
    const uint32_t* Kg = g_Kh + (size_t)nh * KVL * 32;
    const uint32_t* Vg = g_Vt + (size_t)nh * HD * (KVL / 2);

    /* issue Q (128 rows x 128B) + K/V chunk 0 into buf 0 */
    #pragma unroll
    for (int i = 0; i < 4; i++) {
        int cid = tid + 256 * i, r = cid >> 3, seg = cid & 7;
        cp16(QSb + (r * PH_PITCH + seg * 4) * 4, Qg + r * 32 + seg * 4);
    }
    #pragma unroll
    for (int i = 0; i < 2; i++) {
        int cid = tid + 256 * i, r = cid >> 3, seg = cid & 7;
        cp16(KSb + (r * PH_PITCH + seg * 4) * 4, Kg + r * 32 + seg * 4);
        cp16(VSb + (r * PH_PITCH + seg * 4) * 4,
             Vg + (size_t)r * (KVL / 2) + seg * 4);
    }
    CP_COMMIT();
    CP_WAIT0();
    __syncthreads();

    /* resident Q A-fragments: 4 ks16 x 4 regs */
    uint32_t aQ[4][4];
    {
        int rb = w * 16;
        #pragma unroll
        for (int ks = 0; ks < 4; ks++) {
            const uint32_t* p0 = QS + (rb + g) * PH_PITCH + ks * 8 + c;
            const uint32_t* p1 = p0 + 8 * PH_PITCH;
            aQ[ks][0] = p0[0]; aQ[ks][2] = p0[4];
            aQ[ks][1] = p1[0]; aQ[ks][3] = p1[4];
        }
    }

    float Oa[8][4];
    #pragma unroll
    for (int i = 0; i < 8; i++)
        #pragma unroll
        for (int j = 0; j < 4; j++) Oa[i][j] = 0.0f;
    float rs0 = 0.0f, rs1 = 0.0f;

    const unsigned long long* mbase = (const unsigned long long*)g_maskbits;
    const unsigned long long* mp0 =
        mbase + (size_t)(n * QL + q0 + w * 16 + g) * 32;
    const unsigned long long* mp1 = mp0 + 8 * 32;

    for (int ch = 0; ch < NCHUNK; ch++) {
        const int p = ch & 1;
        const uint32_t* KS = smK + p * 2304;
        const uint32_t* VS = smV + p * 2304;

        if (ch > 0) {
            CP_WAIT0();
            __syncthreads();
        }
        if (ch + 1 < NCHUNK) {
            const uint32_t kb2 = KSb + (1 - p) * 2304 * 4;
            const uint32_t vb2 = VSb + (1 - p) * 2304 * 4;
            const uint32_t* Kn = Kg + (size_t)(ch + 1) * 64 * 32;
            const uint32_t* Vn = Vg + (ch + 1) * 32;
            #pragma unroll
            for (int i = 0; i < 2; i++) {
                int cid = tid + 256 * i, r = cid >> 3, seg = cid & 7;
                cp16(kb2 + (r * PH_PITCH + seg * 4) * 4, Kn + r * 32 + seg * 4);
                cp16(vb2 + (r * PH_PITCH + seg * 4) * 4,
                     Vn + (size_t)r * (KVL / 2) + seg * 4);
            }
            CP_COMMIT();
        }

        unsigned long long m0 = mp0[ch];
        unsigned long long m1 = mp1[ch];

        /* ---- per nsp (16 kv): QK -> softmax (registers) -> PV */
        #pragma unroll
        for (int nsp = 0; nsp < 4; nsp++) {
            float S[2][4];
            #pragma unroll
            for (int nn = 0; nn < 2; nn++)
                #pragma unroll
                for (int j = 0; j < 4; j++) S[nn][j] = 0.0f;

            #pragma unroll
            for (int ks = 0; ks < 4; ks++) {
                #pragma unroll
                for (int nn = 0; nn < 2; nn++) {
                    int ns = nsp * 2 + nn;
                    const uint32_t* bp = KS + (ns * 8 + g) * PH_PITCH + ks * 8 + c;
                    mma16(S[nn], aQ[ks], bp[0], bp[4]);
                }
            }

            uint32_t aP[4];
            #pragma unroll
            for (int nn = 0; nn < 2; nn++) {
                int ns = nsp * 2 + nn;
                int sh = ns * 8 + 2 * c;
                uint32_t bm0 = (uint32_t)(m0 >> sh);
                uint32_t bm1 = (uint32_t)(m1 >> sh);
                float e0 = (bm0 & 1u) ? ex2f(S[nn][0] * K2E) : 0.0f;
                float e1 = (bm0 & 2u) ? ex2f(S[nn][1] * K2E) : 0.0f;
                float e2 = (bm1 & 1u) ? ex2f(S[nn][2] * K2E) : 0.0f;
                float e3 = (bm1 & 2u) ? ex2f(S[nn][3] * K2E) : 0.0f;
                rs0 += e0 + e1;
                rs1 += e2 + e3;
                aP[2 * nn]     = pack2(e0, e1);
                aP[2 * nn + 1] = pack2(e2, e3);
            }

            #pragma unroll
            for (int ds = 0; ds < 8; ds++) {
                const uint32_t* vp = VS + (ds * 8 + g) * PH_PITCH + nsp * 8 + c;
                mma16(Oa[ds], aP, vp[0], vp[4]);
            }
        }
    }

    /* row-sum reduce across quad, normalize, write fp16 to g_Xh */
    rs0 += __shfl_xor_sync(0xffffffffu, rs0, 1);
    rs0 += __shfl_xor_sync(0xffffffffu, rs0, 2);
    rs1 += __shfl_xor_sync(0xffffffffu, rs1, 1);
    rs1 += __shfl_xor_sync(0xffffffffu, rs1, 2);
    float inv0 = 1.0f / rs0, inv1 = 1.0f / rs1;

    uint32_t* x0 = g_Xh + (size_t)(n * QL + q0 + w * 16 + g) * 512
                 + (nh & 15) * 32;
    uint32_t* x1 = x0 + 8 * 512;
    #pragma unroll
    for (int ds = 0; ds < 8; ds++) {
        x0[ds * 4 + c] = pack2(Oa[ds][0] * inv0, Oa[ds][1] * inv0);
        x1[ds * 4 + c] = pack2(Oa[ds][2] * inv1, Oa[ds][3] * inv1);
    }
}

/* ------ projection Y = Xh Wh^T + b : cp.async double-buffer, KT=64 ------- */
__global__ __launch_bounds__(256, 2) void proj_mma(const float* __restrict__ bias,
                                                   float* __restrict__ Y)
{
    extern __shared__ uint32_t ps[];
    uint32_t* XB = ps;             /* 2 bufs @ 0, 4608 (words) */
    uint32_t* WB = ps + 9216;      /* 2 bufs @ 9216, 13824     */
    const uint32_t sb = smem_u32(ps);
    const uint32_t XBb = sb, WBb = sb + 9216 * 4;

    const int tid = threadIdx.x, w = tid >> 5, lane = tid & 31;
    const int g = lane >> 2, c = lane & 3;
    const int wm = w & 3, wn = w >> 2;
    const int m0 = blockIdx.y * 128, n0 = blockIdx.x * 128;

    const uint32_t* Xg = g_Xh + (size_t)m0 * 512;
    const uint32_t* Wg = g_Wh + (size_t)n0 * 512;

    float D[2][8][4];
    #pragma unroll
    for (int a = 0; a < 2; a++)
        #pragma unroll
        for (int i = 0; i < 8; i++)
            #pragma unroll
            for (int j = 0; j < 4; j++) D[a][i][j] = 0.0f;

    /* stage k-tile 0 into buf 0 */
    #pragma unroll
    for (int i = 0; i < 4; i++) {
        int cid = tid + 256 * i, r = cid >> 3, seg = cid & 7;
        cp16(XBb + (r * PH_PITCH + seg * 4) * 4, Xg + r * 512 + seg * 4);
        cp16(WBb + (r * PH_PITCH + seg * 4) * 4, Wg + r * 512 + seg * 4);
    }
    CP_COMMIT();

    for (int kt = 0; kt < 16; kt++) {
        const int p = kt & 1;
        CP_WAIT0();
        __syncthreads();
        if (kt + 1 < 16) {
            const uint32_t xb2 = XBb + (1 - p) * 4608 * 4;
            const uint32_t wb2 = WBb + (1 - p) * 4608 * 4;
            int koff = (kt + 1) * 32;
            #pragma unroll
            for (int i = 0; i < 4; i++) {
                int cid = tid + 256 * i, r = cid >> 3, seg = cid & 7;
                cp16(xb2 + (r * PH_PITCH + seg * 4) * 4,
                     Xg + r * 512 + koff + seg * 4);
                cp16(wb2 + (r * PH_PITCH + seg * 4) * 4,
                     Wg + r * 512 + koff + seg * 4);
            }
            CP_COMMIT();
        }

        const uint32_t* XS = XB + p * 4608;
        const uint32_t* WS = WB + p * 4608;
        #pragma unroll
        for (int ks = 0; ks < 4; ks++) {
            uint32_t A[2][4];
            #pragma unroll
            for (int mi = 0; mi < 2; mi++) {
                int rb = wm * 32 + mi * 16;
                const uint32_t* p0 = XS + (rb + g) * PH_PITCH + ks * 8 + c;
                const uint32_t* p1 = XS + (rb + g + 8) * PH_PITCH + ks * 8 + c;
                A[mi][0] = p0[0]; A[mi][2] = p0[4];
                A[mi][1] = p1[0]; A[mi][3] = p1[4];
            }
            #pragma unroll
            for (int ns = 0; ns < 8; ns++) {
                const uint32_t* bp =
                    WS + (wn * 64 + ns * 8 + g) * PH_PITCH + ks * 8 + c;
                uint32_t b0 = bp[0], b1 = bp[4];
                mma16(D[0][ns], A[0], b0, b1);
                mma16(D[1][ns], A[1], b0, b1);
            }
        }
        __syncthreads();   /* reads of buf p done before its next overwrite */
    }

    #pragma unroll
    for (int mi = 0; mi < 2; mi++) {
        int row0 = m0 + wm * 32 + mi * 16 + g;
        #pragma unroll
        for (int ns = 0; ns < 8; ns++) {
            int col = n0 + wn * 64 + ns * 8 + 2 * c;
            float2 bv = *(const float2*)(bias + col);
            *(float2*)(Y + (size_t)row0 * ED + col) =
                make_float2(D[mi][ns][0] + bv.x, D[mi][ns][1] + bv.y);
            *(float2*)(Y + (size_t)(row0 + 8) * ED + col) =
                make_float2(D[mi][ns][2] + bv.x, D[mi][ns][3] + bv.y);
        }
    }
}

/* --------------------------------- launch -------------------------------- */
extern "C" void kernel_launch(void* const* d_in, const int* in_sizes, int n_in,
                              void* d_out, int out_size)
{
    const float* q    = (const float*)d_in[0];
    const float* k    = (const float*)d_in[1];
    const float* v    = (const float*)d_in[2];
    const int*   mask = (const int*)  d_in[3];
    const float* W    = (const float*)d_in[4];
    const float* b    = (const float*)d_in[5];
    float* out = (float*)d_out;

    const int smem_attn = 13824 * 4;   /* 55296 */
    const int smem_proj = 18432 * 4;   /* 73728 */
    cudaFuncSetAttribute(attn_mma, cudaFuncAttributeMaxDynamicSharedMemorySize, smem_attn);
    cudaFuncSetAttribute(proj_mma, cudaFuncAttributeMaxDynamicSharedMemorySize, smem_proj);

    maskpack<<<8192, 256>>>(mask);
    convQK<<<dim3(16, 64), 256>>>(q, k);
    convV<<<dim3(32, 64), 256>>>(v);
    convW<<<1024, 256>>>(W);

    attn_mma<<<dim3(QL / BQ, NH), 256, smem_attn>>>();

    proj_mma<<<dim3(ED / 128, (NBATCH * QL) / 128), 256, smem_proj>>>(b, out);
}